// round 6
// baseline (speedup 1.0000x reference)
#include <cuda_runtime.h>
#include <cstdint>
#include <math.h>

#define B_    1024
#define DIN_  343
#define DH_   342
#define H_    512
#define DOUT_ 311
#define NP2_  320

#define S0_   352            // per-control K stride, layer 0 (11 chunks of 32)
#define K0P_  1408           // 4 * 352
#define S1_   544            // 512 h + 1 bias + 31 pad (17 chunks of 32)
#define K1P_  2176           // 4 * 544

// ---- scratch ----
__device__ float g_z0[B_ * K0P_];
__device__ float g_z1[B_ * K1P_];
__device__ float g_z2[B_ * K1P_];
__device__ float g_w0[H_ * K0P_];
__device__ float g_w1[H_ * K1P_];
__device__ float g_w2[NP2_ * K1P_];
__device__ float g_coef[B_ * 4];
__device__ float g_p[4][B_ * H_];    // split-K partials (one per control stripe)

// ---------------- helpers ----------------
__device__ __forceinline__ float to_tf32(float v) {
    uint32_t o; asm("cvt.rna.tf32.f32 %0, %1;" : "=r"(o) : "f"(v));
    return __uint_as_float(o);
}
__device__ __forceinline__ float elu1(float v) { return v > 0.0f ? v : expm1f(v); }

__device__ __forceinline__ uint32_t smem_u32(const void* p) {
    uint32_t a;
    asm("{ .reg .u64 t; cvta.to.shared.u64 t, %1; cvt.u32.u64 %0, t; }" : "=r"(a) : "l"(p));
    return a;
}
__device__ __forceinline__ void cp16(uint32_t dst, const float* src) {
    asm volatile("cp.async.cg.shared.global [%0], [%1], 16;" :: "r"(dst), "l"(src) : "memory");
}
__device__ __forceinline__ void cp_commit() { asm volatile("cp.async.commit_group;" ::: "memory"); }
template <int N> __device__ __forceinline__ void cp_wait() {
    asm volatile("cp.async.wait_group %0;" :: "n"(N) : "memory");
}
__device__ __forceinline__ void ldsm4(uint32_t* r, uint32_t addr) {
    asm volatile("ldmatrix.sync.aligned.m8n8.x4.shared.b16 {%0,%1,%2,%3}, [%4];"
                 : "=r"(r[0]), "=r"(r[1]), "=r"(r[2]), "=r"(r[3]) : "r"(addr));
}
__device__ __forceinline__ void mma8(float* c, const uint32_t* a, uint32_t b0, uint32_t b1) {
    asm volatile(
        "mma.sync.aligned.m16n8k8.row.col.f32.tf32.tf32.f32 "
        "{%0,%1,%2,%3}, {%4,%5,%6,%7}, {%8,%9}, {%0,%1,%2,%3};"
        : "+f"(c[0]), "+f"(c[1]), "+f"(c[2]), "+f"(c[3])
        : "r"(a[0]), "r"(a[1]), "r"(a[2]), "r"(a[3]), "r"(b0), "r"(b1));
}

// ---------------- prep kernels ----------------
__global__ void k_coef(const float* __restrict__ x) {
    int b = blockIdx.x * blockDim.x + threadIdx.x;
    if (b >= B_) return;
    float ps = 4.0f * x[b * DIN_ + (DIN_ - 1)];
    float mu = ps - floorf(ps);
    int   k1 = ((int)ps) & 3;
    float m2 = mu * mu, m3 = m2 * mu;
    float a0 = -0.5f * m3 +        m2 - 0.5f * mu;
    float a1 =  1.5f * m3 - 2.5f * m2 + 1.0f;
    float a2 = -1.5f * m3 + 2.0f * m2 + 0.5f * mu;
    float a3 =  0.5f * m3 - 0.5f * m2;
    float c[4];
    c[(k1 + 3) & 3] = a0;
    c[k1]           = a1;
    c[(k1 + 1) & 3] = a2;
    c[(k1 + 2) & 3] = a3;
#pragma unroll
    for (int j = 0; j < 4; j++) {
        g_coef[b * 4 + j] = c[j];
        float ct = to_tf32(c[j]);
        size_t base = (size_t)b * K1P_ + j * S1_;
        g_z1[base + 512] = ct;
        g_z2[base + 512] = ct;
        for (int p = 513; p < S1_; p++) { g_z1[base + p] = 0.0f; g_z2[base + p] = 0.0f; }
    }
}

__global__ void k_z0(const float* __restrict__ x) {
    int b = blockIdx.x;
    float4 cf = *(const float4*)&g_coef[b * 4];
    float cc[4] = {cf.x, cf.y, cf.z, cf.w};
    const float* xr = x + (size_t)b * DIN_;
    float* z = g_z0 + (size_t)b * K0P_;
    for (int i = threadIdx.x; i < S0_; i += blockDim.x) {
        float v0, v1, v2, v3;
        if (i < DH_) {
            float v = xr[i];
            v0 = to_tf32(cc[0] * v); v1 = to_tf32(cc[1] * v);
            v2 = to_tf32(cc[2] * v); v3 = to_tf32(cc[3] * v);
        } else if (i == DH_) {
            v0 = to_tf32(cc[0]); v1 = to_tf32(cc[1]);
            v2 = to_tf32(cc[2]); v3 = to_tf32(cc[3]);
        } else { v0 = v1 = v2 = v3 = 0.0f; }
        z[0 * S0_ + i] = v0; z[1 * S0_ + i] = v1;
        z[2 * S0_ + i] = v2; z[3 * S0_ + i] = v3;
    }
}

// one CTA per (o-row, control): grid (1344, 4), 128 threads
__global__ void k_wall(const float* __restrict__ W0, const float* __restrict__ W1,
                       const float* __restrict__ W2, const float* __restrict__ b0,
                       const float* __restrict__ b1, const float* __restrict__ b2) {
    int blk = blockIdx.x;
    int c = blockIdx.y;
    if (blk < 512) {
        int o = blk;
        const float* src = W0 + ((size_t)(c * H_ + o)) * DH_;
        float bias = b0[c * H_ + o];
        float* dst = g_w0 + (size_t)o * K0P_ + c * S0_;
        for (int i = threadIdx.x; i < S0_; i += blockDim.x) {
            float v = (i < DH_) ? src[i] : (i == DH_ ? bias : 0.0f);
            dst[i] = to_tf32(v);
        }
    } else if (blk < 1024) {
        int o = blk - 512;
        const float* src = W1 + ((size_t)(c * H_ + o)) * H_;
        float bias = b1[c * H_ + o];
        float* dst = g_w1 + (size_t)o * K1P_ + c * S1_;
        for (int i = threadIdx.x; i < S1_; i += blockDim.x) {
            float v = (i < H_) ? src[i] : (i == H_ ? bias : 0.0f);
            dst[i] = to_tf32(v);
        }
    } else {
        int o = blk - 1024;
        bool valid = (o < DOUT_);
        const float* src = W2 + ((size_t)(c * DOUT_ + o)) * H_;
        float bias = valid ? b2[c * DOUT_ + o] : 0.0f;
        float* dst = g_w2 + (size_t)o * K1P_ + c * S1_;
        for (int i = threadIdx.x; i < S1_; i += blockDim.x) {
            float v = 0.0f;
            if (valid) v = (i < H_) ? src[i] : (i == H_ ? bias : 0.0f);
            dst[i] = to_tf32(v);
        }
    }
}

// ---------------- tf32 mma.sync GEMM, split-K x4 (per control stripe) ----------
// CTA 128x64, 8 warps (4M x 2N), warp tile 32x32, k-chunk 32, 3-stage cp.async.
// Stage layout: A = 16 rowblocks x 8 k4 x 128B (16KB), B = 8 rowblocks (8KB).

#define NS 3
#define STG 24576u

__device__ __forceinline__ void fill_stage(uint32_t sdst, const float* __restrict__ A,
                                           const float* __restrict__ Bw,
                                           int bm, int bn, int KP, int k0, int t) {
#pragma unroll
    for (int j = 0; j < 4; j++) {
        int f = t + j * 256;
        int m = f >> 3, k4 = f & 7;
        uint32_t off = (uint32_t)((((m >> 3) * 8 + k4) * 128) + (((m & 7) ^ k4) * 16));
        cp16(sdst + off, A + (size_t)(bm + m) * KP + k0 + k4 * 4);
    }
#pragma unroll
    for (int j = 0; j < 2; j++) {
        int f = t + j * 256;
        int m = f >> 3, k4 = f & 7;
        uint32_t off = (uint32_t)((((m >> 3) * 8 + k4) * 128) + (((m & 7) ^ k4) * 16));
        cp16(sdst + 16384u + off, Bw + (size_t)(bn + m) * KP + k0 + k4 * 4);
    }
}

template <int LAYER>
__global__ void __launch_bounds__(256) k_gemm() {
    constexpr int KP   = (LAYER == 0) ? K0P_ : K1P_;
    constexpr int S    = (LAYER == 0) ? S0_ : S1_;
    constexpr int NIT  = S / 32;
    constexpr int NP   = (LAYER == 2) ? NP2_ : H_;
    const float* __restrict__ A  = (LAYER == 0) ? g_z0 : (LAYER == 1 ? g_z1 : g_z2);
    const float* __restrict__ Bw = (LAYER == 0) ? g_w0 : (LAYER == 1 ? g_w1 : g_w2);

    extern __shared__ float smem[];
    uint32_t sbase = smem_u32(smem);

    const int t = threadIdx.x, lane = t & 31, wid = t >> 5;
    const int wm = (wid >> 1) * 32, wn = (wid & 1) * 32;
    const int bm = blockIdx.y * 128, bn = blockIdx.x * 64;
    const int kbase = blockIdx.z * S;
    float* __restrict__ dst = g_p[blockIdx.z];
    const int g = lane >> 3, r = lane & 7;
    const int ga = g & 1, gb = g >> 1;
    const int wm8 = wm >> 3, wn8 = wn >> 3;

    float acc[2][4][4] = {};

    fill_stage(sbase, A, Bw, bm, bn, KP, kbase, t);
    cp_commit();
    fill_stage(sbase + STG, A, Bw, bm, bn, KP, kbase + 32, t);
    cp_commit();

#pragma unroll 1
    for (int it = 0; it < NIT; it++) {
        int s = it % NS;
        cp_wait<NS - 2>();
        __syncthreads();
        if (it + NS - 1 < NIT) {
            fill_stage(sbase + (uint32_t)((it + NS - 1) % NS) * STG,
                       A, Bw, bm, bn, KP, kbase + (it + NS - 1) * 32, t);
        }
        cp_commit();

        uint32_t sa  = sbase + (uint32_t)s * STG;
        uint32_t sbB = sa + 16384u;
#pragma unroll
        for (int ki2 = 0; ki2 < 4; ki2++) {
            int k4a = ki2 * 2 + gb;
            int k4b = ki2 * 2 + ga;
            uint32_t a0[4], a1[4], b0[4], b1[4];
            ldsm4(a0, sa  + (uint32_t)((((wm8 + ga) * 8 + k4a) * 128) + ((r ^ k4a) * 16)));
            ldsm4(a1, sa  + (uint32_t)((((wm8 + 2 + ga) * 8 + k4a) * 128) + ((r ^ k4a) * 16)));
            ldsm4(b0, sbB + (uint32_t)((((wn8 + gb) * 8 + k4b) * 128) + ((r ^ k4b) * 16)));
            ldsm4(b1, sbB + (uint32_t)((((wn8 + 2 + gb) * 8 + k4b) * 128) + ((r ^ k4b) * 16)));
            mma8(acc[0][0], a0, b0[0], b0[1]);
            mma8(acc[0][1], a0, b0[2], b0[3]);
            mma8(acc[0][2], a0, b1[0], b1[1]);
            mma8(acc[0][3], a0, b1[2], b1[3]);
            mma8(acc[1][0], a1, b0[0], b0[1]);
            mma8(acc[1][1], a1, b0[2], b0[3]);
            mma8(acc[1][2], a1, b1[0], b1[1]);
            mma8(acc[1][3], a1, b1[2], b1[3]);
        }
    }

    // store raw partials
#pragma unroll
    for (int mt = 0; mt < 2; mt++) {
        int m0 = bm + wm + mt * 16 + (lane >> 2);
        int m1 = m0 + 8;
#pragma unroll
        for (int nt = 0; nt < 4; nt++) {
            int n = bn + wn + nt * 8 + (lane & 3) * 2;
            *(float2*)&dst[(size_t)m0 * NP + n] = make_float2(acc[mt][nt][0], acc[mt][nt][1]);
            *(float2*)&dst[(size_t)m1 * NP + n] = make_float2(acc[mt][nt][2], acc[mt][nt][3]);
        }
    }
}

// ---- epilogue: sum 4 partials, ELU + coef scatter (or final store) ----
template <int LAYER>
__global__ void k_ep(float* __restrict__ out_final) {
    int b = blockIdx.x;
    int tx = threadIdx.x;
    if (LAYER < 2) {
        float4 cf = *(const float4*)&g_coef[b * 4];
        float cc[4] = {cf.x, cf.y, cf.z, cf.w};
        float* zn = ((LAYER == 0) ? g_z1 : g_z2) + (size_t)b * K1P_;
        int n = tx * 4;
        float4 v0 = *(const float4*)&g_p[0][(size_t)b * H_ + n];
        float4 v1 = *(const float4*)&g_p[1][(size_t)b * H_ + n];
        float4 v2 = *(const float4*)&g_p[2][(size_t)b * H_ + n];
        float4 v3 = *(const float4*)&g_p[3][(size_t)b * H_ + n];
        float h0 = elu1(v0.x + v1.x + v2.x + v3.x);
        float h1 = elu1(v0.y + v1.y + v2.y + v3.y);
        float h2 = elu1(v0.z + v1.z + v2.z + v3.z);
        float h3 = elu1(v0.w + v1.w + v2.w + v3.w);
#pragma unroll
        for (int ct = 0; ct < 4; ct++) {
            float4 w = make_float4(to_tf32(cc[ct] * h0), to_tf32(cc[ct] * h1),
                                   to_tf32(cc[ct] * h2), to_tf32(cc[ct] * h3));
            *(float4*)(zn + ct * S1_ + n) = w;
        }
    } else {
        float* o = out_final + (size_t)b * DOUT_;
        for (int n = tx; n < DOUT_; n += blockDim.x)
            o[n] = g_p[0][(size_t)b * NP2_ + n] + g_p[1][(size_t)b * NP2_ + n]
                 + g_p[2][(size_t)b * NP2_ + n] + g_p[3][(size_t)b * NP2_ + n];
    }
}

// ---------------- launch ----------------
extern "C" void kernel_launch(void* const* d_in, const int* in_sizes, int n_in,
                              void* d_out, int out_size) {
    const float* x  = (const float*)d_in[0];
    const float* W0 = (const float*)d_in[1];
    const float* W1 = (const float*)d_in[2];
    const float* W2 = (const float*)d_in[3];
    const float* b0 = (const float*)d_in[4];
    const float* b1 = (const float*)d_in[5];
    const float* b2 = (const float*)d_in[6];
    float* out = (float*)d_out;

    static int smem_set = 0;
    if (!smem_set) {
        cudaFuncSetAttribute(k_gemm<0>, cudaFuncAttributeMaxDynamicSharedMemorySize, NS * STG);
        cudaFuncSetAttribute(k_gemm<1>, cudaFuncAttributeMaxDynamicSharedMemorySize, NS * STG);
        cudaFuncSetAttribute(k_gemm<2>, cudaFuncAttributeMaxDynamicSharedMemorySize, NS * STG);
        smem_set = 1;
    }

    k_coef<<<4, 256>>>(x);
    k_wall<<<dim3(1344, 4), 128>>>(W0, W1, W2, b0, b1, b2);
    k_z0<<<B_, 128>>>(x);

    k_gemm<0><<<dim3(8, 8, 4), 256, NS * STG>>>();
    k_ep<0><<<B_, 128>>>(nullptr);
    k_gemm<1><<<dim3(8, 8, 4), 256, NS * STG>>>();
    k_ep<1><<<B_, 128>>>(nullptr);
    k_gemm<2><<<dim3(5, 8, 4), 256, NS * STG>>>();
    k_ep<2><<<B_, 128>>>(out);
}

// round 7
// speedup vs baseline: 1.7045x; 1.7045x over previous
#include <cuda_runtime.h>
#include <cstdint>
#include <math.h>

#define B_    1024
#define DIN_  343
#define DH_   342
#define H_    512
#define DOUT_ 311
#define NP2_  320
#define K0_   352   // padded K, layer 0 (11 chunks of 32)
#define K1_   512   // K, layers 1/2 (16 chunks of 32)

// ---- scratch ----
__device__ float g_h0[B_ * K0_];
__device__ float g_h1[B_ * K1_];
__device__ float g_h2[B_ * K1_];
__device__ float g_p[4][B_ * H_];    // per-control partials
__device__ float g_coef[B_ * 4];

// ---------------- helpers ----------------
__device__ __forceinline__ float to_tf32(float v) {
    uint32_t o; asm("cvt.rna.tf32.f32 %0, %1;" : "=r"(o) : "f"(v));
    return __uint_as_float(o);
}
__device__ __forceinline__ float elu1(float v) { return v > 0.0f ? v : expm1f(v); }

__device__ __forceinline__ uint32_t smem_u32(const void* p) {
    uint32_t a;
    asm("{ .reg .u64 t; cvta.to.shared.u64 t, %1; cvt.u32.u64 %0, t; }" : "=r"(a) : "l"(p));
    return a;
}
__device__ __forceinline__ void cp16(uint32_t dst, const float* src) {
    asm volatile("cp.async.cg.shared.global [%0], [%1], 16;" :: "r"(dst), "l"(src) : "memory");
}
__device__ __forceinline__ void cp_commit() { asm volatile("cp.async.commit_group;" ::: "memory"); }
template <int N> __device__ __forceinline__ void cp_wait() {
    asm volatile("cp.async.wait_group %0;" :: "n"(N) : "memory");
}
__device__ __forceinline__ void ldsm4(uint32_t* r, uint32_t addr) {
    asm volatile("ldmatrix.sync.aligned.m8n8.x4.shared.b16 {%0,%1,%2,%3}, [%4];"
                 : "=r"(r[0]), "=r"(r[1]), "=r"(r[2]), "=r"(r[3]) : "r"(addr));
}
__device__ __forceinline__ void mma8(float* c, const uint32_t* a, uint32_t b0, uint32_t b1) {
    asm volatile(
        "mma.sync.aligned.m16n8k8.row.col.f32.tf32.tf32.f32 "
        "{%0,%1,%2,%3}, {%4,%5,%6,%7}, {%8,%9}, {%0,%1,%2,%3};"
        : "+f"(c[0]), "+f"(c[1]), "+f"(c[2]), "+f"(c[3])
        : "r"(a[0]), "r"(a[1]), "r"(a[2]), "r"(a[3]), "r"(b0), "r"(b1));
}
__device__ __forceinline__ void sts128(uint32_t addr, float x, float y, float z, float w) {
    asm volatile("st.shared.v4.b32 [%0], {%1,%2,%3,%4};"
                 :: "r"(addr), "r"(__float_as_uint(x)), "r"(__float_as_uint(y)),
                    "r"(__float_as_uint(z)), "r"(__float_as_uint(w)) : "memory");
}

// ---------------- prep kernels ----------------
__global__ void k_coef(const float* __restrict__ x) {
    int b = blockIdx.x * blockDim.x + threadIdx.x;
    if (b >= B_) return;
    float ps = 4.0f * x[b * DIN_ + (DIN_ - 1)];
    float mu = ps - floorf(ps);
    int   k1 = ((int)ps) & 3;
    float m2 = mu * mu, m3 = m2 * mu;
    float a0 = -0.5f * m3 +        m2 - 0.5f * mu;
    float a1 =  1.5f * m3 - 2.5f * m2 + 1.0f;
    float a2 = -1.5f * m3 + 2.0f * m2 + 0.5f * mu;
    float a3 =  0.5f * m3 - 0.5f * m2;
    float c[4];
    c[(k1 + 3) & 3] = a0;
    c[k1]           = a1;
    c[(k1 + 1) & 3] = a2;
    c[(k1 + 2) & 3] = a3;
#pragma unroll
    for (int j = 0; j < 4; j++) g_coef[b * 4 + j] = c[j];
}

// x[:, :342] -> g_h0 (B x 352), tf32-rounded, zero pad
__global__ void k_z0(const float* __restrict__ x) {
    int b = blockIdx.x;
    const float* xr = x + (size_t)b * DIN_;
    float* z = g_h0 + (size_t)b * K0_;
    for (int i = threadIdx.x; i < K0_; i += blockDim.x)
        z[i] = (i < DH_) ? to_tf32(xr[i]) : 0.0f;
}

// ---------------- tf32 mma.sync GEMM, one control per blockIdx.z --------------
// CTA 128x64, 8 warps (4M x 2N), warp tile 32x32, k-chunk 32, 3-stage.
// A via cp.async from plain activation buffer; B read directly from the
// ORIGINAL weight tensor: LDG (pipelined one stage ahead) + cvt.rna.tf32 + STS.

#define NS 3
#define STG 24576u

__device__ __forceinline__ void fillA(uint32_t sdst, const float* __restrict__ A,
                                      int bm, int KP, int k0, int t) {
#pragma unroll
    for (int j = 0; j < 4; j++) {
        int f = t + j * 256;
        int m = f >> 3, k4 = f & 7;
        uint32_t off = (uint32_t)((((m >> 3) * 8 + k4) * 128) + (((m & 7) ^ k4) * 16));
        cp16(sdst + off, A + (size_t)(bm + m) * KP + k0 + k4 * 4);
    }
}

template <int LAYER>
__device__ __forceinline__ void ldgB(float* r, const float* __restrict__ W,
                                     int c, int bn, int k0, int t) {
#pragma unroll
    for (int j = 0; j < 2; j++) {
        int f = t + j * 256;
        int m = f >> 3, k4 = f & 7;
        int o = bn + m;
        if (LAYER == 0) {
            const float* p = W + (size_t)(c * H_ + o) * DH_;
#pragma unroll
            for (int e = 0; e < 4; e++) {
                int col = k0 + k4 * 4 + e;
                r[j * 4 + e] = (col < DH_) ? __ldg(p + col) : 0.0f;
            }
        } else if (LAYER == 1) {
            float4 v = *(const float4*)(W + (size_t)(c * H_ + o) * K1_ + k0 + k4 * 4);
            r[j * 4 + 0] = v.x; r[j * 4 + 1] = v.y; r[j * 4 + 2] = v.z; r[j * 4 + 3] = v.w;
        } else {
            if (o < DOUT_) {
                float4 v = *(const float4*)(W + (size_t)(c * DOUT_ + o) * K1_ + k0 + k4 * 4);
                r[j * 4 + 0] = v.x; r[j * 4 + 1] = v.y; r[j * 4 + 2] = v.z; r[j * 4 + 3] = v.w;
            } else {
                r[j * 4 + 0] = 0.0f; r[j * 4 + 1] = 0.0f; r[j * 4 + 2] = 0.0f; r[j * 4 + 3] = 0.0f;
            }
        }
    }
}

__device__ __forceinline__ void stsB(uint32_t sdst, const float* r, int t) {
#pragma unroll
    for (int j = 0; j < 2; j++) {
        int f = t + j * 256;
        int m = f >> 3, k4 = f & 7;
        uint32_t off = (uint32_t)((((m >> 3) * 8 + k4) * 128) + (((m & 7) ^ k4) * 16));
        sts128(sdst + off, to_tf32(r[j * 4 + 0]), to_tf32(r[j * 4 + 1]),
                           to_tf32(r[j * 4 + 2]), to_tf32(r[j * 4 + 3]));
    }
}

template <int LAYER>
__global__ void __launch_bounds__(256) k_gemm(const float* __restrict__ W) {
    constexpr int KP  = (LAYER == 0) ? K0_ : K1_;
    constexpr int NIT = KP / 32;
    constexpr int NP  = (LAYER == 2) ? NP2_ : H_;
    const float* __restrict__ A = (LAYER == 0) ? g_h0 : (LAYER == 1 ? g_h1 : g_h2);

    extern __shared__ float smem[];
    uint32_t sbase = smem_u32(smem);

    const int t = threadIdx.x, lane = t & 31, wid = t >> 5;
    const int wm = (wid >> 1) * 32, wn = (wid & 1) * 32;
    const int bm = blockIdx.y * 128, bn = blockIdx.x * 64;
    const int c = blockIdx.z;
    float* __restrict__ dst = g_p[c];
    const int g = lane >> 3, r = lane & 7;
    const int ga = g & 1, gb = g >> 1;
    const int wm8 = wm >> 3, wn8 = wn >> 3;

    float acc[2][4][4] = {};
    float rB[8];

    fillA(sbase, A, bm, KP, 0, t);
    cp_commit();
    fillA(sbase + STG, A, bm, KP, 32, t);
    cp_commit();
    ldgB<LAYER>(rB, W, c, bn, 0, t);
    stsB(sbase + 16384u, rB, t);
    ldgB<LAYER>(rB, W, c, bn, 32, t);

#pragma unroll 1
    for (int it = 0; it < NIT; it++) {
        int s = it % NS;
        cp_wait<NS - 2>();
        __syncthreads();
        if (it + 2 < NIT)
            fillA(sbase + (uint32_t)((it + 2) % NS) * STG, A, bm, KP, (it + 2) * 32, t);
        cp_commit();

        uint32_t sa  = sbase + (uint32_t)s * STG;
        uint32_t sbB = sa + 16384u;
#pragma unroll
        for (int ki2 = 0; ki2 < 4; ki2++) {
            int k4a = ki2 * 2 + gb;
            int k4b = ki2 * 2 + ga;
            uint32_t a0[4], a1[4], b0[4], b1[4];
            ldsm4(a0, sa  + (uint32_t)((((wm8 + ga) * 8 + k4a) * 128) + ((r ^ k4a) * 16)));
            ldsm4(a1, sa  + (uint32_t)((((wm8 + 2 + ga) * 8 + k4a) * 128) + ((r ^ k4a) * 16)));
            ldsm4(b0, sbB + (uint32_t)((((wn8 + gb) * 8 + k4b) * 128) + ((r ^ k4b) * 16)));
            ldsm4(b1, sbB + (uint32_t)((((wn8 + 2 + gb) * 8 + k4b) * 128) + ((r ^ k4b) * 16)));
            mma8(acc[0][0], a0, b0[0], b0[1]);
            mma8(acc[0][1], a0, b0[2], b0[3]);
            mma8(acc[0][2], a0, b1[0], b1[1]);
            mma8(acc[0][3], a0, b1[2], b1[3]);
            mma8(acc[1][0], a1, b0[0], b0[1]);
            mma8(acc[1][1], a1, b0[2], b0[3]);
            mma8(acc[1][2], a1, b1[0], b1[1]);
            mma8(acc[1][3], a1, b1[2], b1[3]);
        }

        if (it + 1 < NIT) stsB(sbase + (uint32_t)((it + 1) % NS) * STG + 16384u, rB, t);
        if (it + 2 < NIT) ldgB<LAYER>(rB, W, c, bn, (it + 2) * 32, t);
    }

    // store coef-scaled partials
#pragma unroll
    for (int mt = 0; mt < 2; mt++) {
        int m0 = bm + wm + mt * 16 + (lane >> 2);
        int m1 = m0 + 8;
        float cs0 = g_coef[m0 * 4 + c];
        float cs1 = g_coef[m1 * 4 + c];
#pragma unroll
        for (int nt = 0; nt < 4; nt++) {
            int n = bn + wn + nt * 8 + (lane & 3) * 2;
            *(float2*)&dst[(size_t)m0 * NP + n] =
                make_float2(acc[mt][nt][0] * cs0, acc[mt][nt][1] * cs0);
            *(float2*)&dst[(size_t)m1 * NP + n] =
                make_float2(acc[mt][nt][2] * cs1, acc[mt][nt][3] * cs1);
        }
    }
}

// ---- epilogue: sum 4 partials + coef-weighted bias, ELU / final ----
template <int LAYER>
__global__ void k_ep(const float* __restrict__ bias, float* __restrict__ out_final) {
    int b = blockIdx.x;
    int tx = threadIdx.x;
    float4 cf = *(const float4*)&g_coef[b * 4];
    float cc[4] = {cf.x, cf.y, cf.z, cf.w};
    if (LAYER < 2) {
        int n = tx * 4;
        float4 v0 = *(const float4*)&g_p[0][(size_t)b * H_ + n];
        float4 v1 = *(const float4*)&g_p[1][(size_t)b * H_ + n];
        float4 v2 = *(const float4*)&g_p[2][(size_t)b * H_ + n];
        float4 v3 = *(const float4*)&g_p[3][(size_t)b * H_ + n];
        float s0 = v0.x + v1.x + v2.x + v3.x;
        float s1 = v0.y + v1.y + v2.y + v3.y;
        float s2 = v0.z + v1.z + v2.z + v3.z;
        float s3 = v0.w + v1.w + v2.w + v3.w;
#pragma unroll
        for (int ct = 0; ct < 4; ct++) {
            float4 bb = *(const float4*)&bias[ct * H_ + n];
            s0 += cc[ct] * bb.x; s1 += cc[ct] * bb.y;
            s2 += cc[ct] * bb.z; s3 += cc[ct] * bb.w;
        }
        float* zn = ((LAYER == 0) ? g_h1 : g_h2) + (size_t)b * K1_;
        float4 w = make_float4(to_tf32(elu1(s0)), to_tf32(elu1(s1)),
                               to_tf32(elu1(s2)), to_tf32(elu1(s3)));
        *(float4*)(zn + n) = w;
    } else {
        float* o = out_final + (size_t)b * DOUT_;
        for (int n = tx; n < DOUT_; n += blockDim.x) {
            float s = g_p[0][(size_t)b * NP2_ + n] + g_p[1][(size_t)b * NP2_ + n]
                    + g_p[2][(size_t)b * NP2_ + n] + g_p[3][(size_t)b * NP2_ + n];
#pragma unroll
            for (int ct = 0; ct < 4; ct++) s += cc[ct] * bias[ct * DOUT_ + n];
            o[n] = s;
        }
    }
}

// ---------------- launch ----------------
extern "C" void kernel_launch(void* const* d_in, const int* in_sizes, int n_in,
                              void* d_out, int out_size) {
    const float* x  = (const float*)d_in[0];
    const float* W0 = (const float*)d_in[1];
    const float* W1 = (const float*)d_in[2];
    const float* W2 = (const float*)d_in[3];
    const float* b0 = (const float*)d_in[4];
    const float* b1 = (const float*)d_in[5];
    const float* b2 = (const float*)d_in[6];
    float* out = (float*)d_out;

    static int smem_set = 0;
    if (!smem_set) {
        cudaFuncSetAttribute(k_gemm<0>, cudaFuncAttributeMaxDynamicSharedMemorySize, NS * STG);
        cudaFuncSetAttribute(k_gemm<1>, cudaFuncAttributeMaxDynamicSharedMemorySize, NS * STG);
        cudaFuncSetAttribute(k_gemm<2>, cudaFuncAttributeMaxDynamicSharedMemorySize, NS * STG);
        smem_set = 1;
    }

    k_coef<<<4, 256>>>(x);
    k_z0<<<B_, 128>>>(x);

    k_gemm<0><<<dim3(8, 8, 4), 256, NS * STG>>>(W0);
    k_ep<0><<<B_, 128>>>(b0, nullptr);
    k_gemm<1><<<dim3(8, 8, 4), 256, NS * STG>>>(W1);
    k_ep<1><<<B_, 128>>>(b1, nullptr);
    k_gemm<2><<<dim3(5, 8, 4), 256, NS * STG>>>(W2);
    k_ep<2><<<B_, 128>>>(b2, out);
}

// round 8
// speedup vs baseline: 1.7529x; 1.0284x over previous
#include <cuda_runtime.h>
#include <cstdint>
#include <math.h>

#define B_    1024
#define DIN_  343
#define DH_   342
#define H_    512
#define DOUT_ 311
#define NP2_  320
#define K0_   352   // padded K, layer 0 (11 chunks of 32)
#define K1_   512   // K, layers 1/2 (16 chunks of 32)

// ---- scratch ----
__device__ float g_h0[B_ * K0_];
__device__ float g_h1[B_ * K1_];
__device__ float g_h2[B_ * K1_];
__device__ float g_p[4][B_ * H_];    // per-control partials
__device__ float g_coef[B_ * 4];

// ---------------- helpers ----------------
__device__ __forceinline__ float to_tf32(float v) {
    uint32_t o; asm("cvt.rna.tf32.f32 %0, %1;" : "=r"(o) : "f"(v));
    return __uint_as_float(o);
}
__device__ __forceinline__ float elu1(float v) { return v > 0.0f ? v : expm1f(v); }

__device__ __forceinline__ uint32_t smem_u32(const void* p) {
    uint32_t a;
    asm("{ .reg .u64 t; cvta.to.shared.u64 t, %1; cvt.u32.u64 %0, t; }" : "=r"(a) : "l"(p));
    return a;
}
__device__ __forceinline__ void cp16(uint32_t dst, const float* src) {
    asm volatile("cp.async.cg.shared.global [%0], [%1], 16;" :: "r"(dst), "l"(src) : "memory");
}
__device__ __forceinline__ void cp_commit() { asm volatile("cp.async.commit_group;" ::: "memory"); }
template <int N> __device__ __forceinline__ void cp_wait() {
    asm volatile("cp.async.wait_group %0;" :: "n"(N) : "memory");
}
__device__ __forceinline__ void ldsm4(uint32_t* r, uint32_t addr) {
    asm volatile("ldmatrix.sync.aligned.m8n8.x4.shared.b16 {%0,%1,%2,%3}, [%4];"
                 : "=r"(r[0]), "=r"(r[1]), "=r"(r[2]), "=r"(r[3]) : "r"(addr));
}
__device__ __forceinline__ void mma8(float* c, const uint32_t* a, uint32_t b0, uint32_t b1) {
    asm volatile(
        "mma.sync.aligned.m16n8k8.row.col.f32.tf32.tf32.f32 "
        "{%0,%1,%2,%3}, {%4,%5,%6,%7}, {%8,%9}, {%0,%1,%2,%3};"
        : "+f"(c[0]), "+f"(c[1]), "+f"(c[2]), "+f"(c[3])
        : "r"(a[0]), "r"(a[1]), "r"(a[2]), "r"(a[3]), "r"(b0), "r"(b1));
}
__device__ __forceinline__ void sts128(uint32_t addr, float x, float y, float z, float w) {
    asm volatile("st.shared.v4.b32 [%0], {%1,%2,%3,%4};"
                 :: "r"(addr), "r"(__float_as_uint(x)), "r"(__float_as_uint(y)),
                    "r"(__float_as_uint(z)), "r"(__float_as_uint(w)) : "memory");
}

// ---------------- prep: coef + x -> g_h0 (fused) ----------------
__global__ void k_z0(const float* __restrict__ x) {
    int b = blockIdx.x;
    const float* xr = x + (size_t)b * DIN_;
    float ps = 4.0f * xr[DIN_ - 1];
    float mu = ps - floorf(ps);
    int   k1 = ((int)ps) & 3;
    float m2 = mu * mu, m3 = m2 * mu;
    float a0 = -0.5f * m3 +        m2 - 0.5f * mu;
    float a1 =  1.5f * m3 - 2.5f * m2 + 1.0f;
    float a2 = -1.5f * m3 + 2.0f * m2 + 0.5f * mu;
    float a3 =  0.5f * m3 - 0.5f * m2;
    float c[4];
    c[(k1 + 3) & 3] = a0;
    c[k1]           = a1;
    c[(k1 + 1) & 3] = a2;
    c[(k1 + 2) & 3] = a3;
    if (threadIdx.x < 4) g_coef[b * 4 + threadIdx.x] = c[threadIdx.x];
    float* z = g_h0 + (size_t)b * K0_;
    for (int i = threadIdx.x; i < K0_; i += blockDim.x)
        z[i] = (i < DH_) ? to_tf32(xr[i]) : 0.0f;
}

// ---------------- tf32 mma.sync GEMM, one control per blockIdx.z --------------
// CTA 128x64, 8 warps (4M x 2N), warp tile 32x32, k-chunk 32, 3-stage.
// A via cp.async; B direct from original weight tensor (LDG pipelined + STS).
// Inner loop: register double-buffered ldmatrix fragments.

#define NS 3
#define STG 24576u

__device__ __forceinline__ void fillA(uint32_t sdst, const float* __restrict__ A,
                                      int bm, int KP, int k0, int t) {
#pragma unroll
    for (int j = 0; j < 4; j++) {
        int f = t + j * 256;
        int m = f >> 3, k4 = f & 7;
        uint32_t off = (uint32_t)((((m >> 3) * 8 + k4) * 128) + (((m & 7) ^ k4) * 16));
        cp16(sdst + off, A + (size_t)(bm + m) * KP + k0 + k4 * 4);
    }
}

template <int LAYER>
__device__ __forceinline__ void ldgB(float* r, const float* __restrict__ W,
                                     int c, int bn, int k0, int t) {
#pragma unroll
    for (int j = 0; j < 2; j++) {
        int f = t + j * 256;
        int m = f >> 3, k4 = f & 7;
        int o = bn + m;
        if (LAYER == 0) {
            const float* p = W + (size_t)(c * H_ + o) * DH_;
#pragma unroll
            for (int e = 0; e < 4; e++) {
                int col = k0 + k4 * 4 + e;
                r[j * 4 + e] = (col < DH_) ? __ldg(p + col) : 0.0f;
            }
        } else if (LAYER == 1) {
            float4 v = *(const float4*)(W + (size_t)(c * H_ + o) * K1_ + k0 + k4 * 4);
            r[j * 4 + 0] = v.x; r[j * 4 + 1] = v.y; r[j * 4 + 2] = v.z; r[j * 4 + 3] = v.w;
        } else {
            if (o < DOUT_) {
                float4 v = *(const float4*)(W + (size_t)(c * DOUT_ + o) * K1_ + k0 + k4 * 4);
                r[j * 4 + 0] = v.x; r[j * 4 + 1] = v.y; r[j * 4 + 2] = v.z; r[j * 4 + 3] = v.w;
            } else {
                r[j * 4 + 0] = 0.0f; r[j * 4 + 1] = 0.0f; r[j * 4 + 2] = 0.0f; r[j * 4 + 3] = 0.0f;
            }
        }
    }
}

__device__ __forceinline__ void stsB(uint32_t sdst, const float* r, int t) {
#pragma unroll
    for (int j = 0; j < 2; j++) {
        int f = t + j * 256;
        int m = f >> 3, k4 = f & 7;
        uint32_t off = (uint32_t)((((m >> 3) * 8 + k4) * 128) + (((m & 7) ^ k4) * 16));
        sts128(sdst + off, to_tf32(r[j * 4 + 0]), to_tf32(r[j * 4 + 1]),
                           to_tf32(r[j * 4 + 2]), to_tf32(r[j * 4 + 3]));
    }
}

template <int LAYER>
__global__ void __launch_bounds__(256, 2) k_gemm(const float* __restrict__ W) {
    constexpr int KP  = (LAYER == 0) ? K0_ : K1_;
    constexpr int NIT = KP / 32;
    constexpr int NP  = (LAYER == 2) ? NP2_ : H_;
    const float* __restrict__ A = (LAYER == 0) ? g_h0 : (LAYER == 1 ? g_h1 : g_h2);

    extern __shared__ float smem[];
    uint32_t sbase = smem_u32(smem);

    const int t = threadIdx.x, lane = t & 31, wid = t >> 5;
    const int wm = (wid >> 1) * 32, wn = (wid & 1) * 32;
    const int bm = blockIdx.y * 128, bn = blockIdx.x * 64;
    const int c = blockIdx.z;
    float* __restrict__ dst = g_p[c];
    const int g = lane >> 3, r = lane & 7;
    const int ga = g & 1, gb = g >> 1;
    const int wm8 = wm >> 3, wn8 = wn >> 3;

    float acc[2][4][4] = {};
    float rB[8];

    fillA(sbase, A, bm, KP, 0, t);
    cp_commit();
    fillA(sbase + STG, A, bm, KP, 32, t);
    cp_commit();
    ldgB<LAYER>(rB, W, c, bn, 0, t);
    stsB(sbase + 16384u, rB, t);
    ldgB<LAYER>(rB, W, c, bn, 32, t);

#pragma unroll 1
    for (int it = 0; it < NIT; it++) {
        int s = it % NS;
        cp_wait<NS - 2>();
        __syncthreads();
        if (it + 2 < NIT)
            fillA(sbase + (uint32_t)((it + 2) % NS) * STG, A, bm, KP, (it + 2) * 32, t);
        cp_commit();

        uint32_t sa  = sbase + (uint32_t)s * STG;
        uint32_t sbB = sa + 16384u;

        uint32_t fa0[2][4], fa1[2][4], fb0[2][4], fb1[2][4];
        {   // prefetch ki2 = 0
            int k4a = gb, k4b = ga;
            ldsm4(fa0[0], sa  + (uint32_t)((((wm8 + ga) * 8 + k4a) * 128) + ((r ^ k4a) * 16)));
            ldsm4(fa1[0], sa  + (uint32_t)((((wm8 + 2 + ga) * 8 + k4a) * 128) + ((r ^ k4a) * 16)));
            ldsm4(fb0[0], sbB + (uint32_t)((((wn8 + gb) * 8 + k4b) * 128) + ((r ^ k4b) * 16)));
            ldsm4(fb1[0], sbB + (uint32_t)((((wn8 + 2 + gb) * 8 + k4b) * 128) + ((r ^ k4b) * 16)));
        }
#pragma unroll
        for (int ki2 = 0; ki2 < 4; ki2++) {
            int cur = ki2 & 1, nxt = cur ^ 1;
            if (ki2 < 3) {
                int k4a = (ki2 + 1) * 2 + gb;
                int k4b = (ki2 + 1) * 2 + ga;
                ldsm4(fa0[nxt], sa  + (uint32_t)((((wm8 + ga) * 8 + k4a) * 128) + ((r ^ k4a) * 16)));
                ldsm4(fa1[nxt], sa  + (uint32_t)((((wm8 + 2 + ga) * 8 + k4a) * 128) + ((r ^ k4a) * 16)));
                ldsm4(fb0[nxt], sbB + (uint32_t)((((wn8 + gb) * 8 + k4b) * 128) + ((r ^ k4b) * 16)));
                ldsm4(fb1[nxt], sbB + (uint32_t)((((wn8 + 2 + gb) * 8 + k4b) * 128) + ((r ^ k4b) * 16)));
            }
            mma8(acc[0][0], fa0[cur], fb0[cur][0], fb0[cur][1]);
            mma8(acc[0][1], fa0[cur], fb0[cur][2], fb0[cur][3]);
            mma8(acc[0][2], fa0[cur], fb1[cur][0], fb1[cur][1]);
            mma8(acc[0][3], fa0[cur], fb1[cur][2], fb1[cur][3]);
            mma8(acc[1][0], fa1[cur], fb0[cur][0], fb0[cur][1]);
            mma8(acc[1][1], fa1[cur], fb0[cur][2], fb0[cur][3]);
            mma8(acc[1][2], fa1[cur], fb1[cur][0], fb1[cur][1]);
            mma8(acc[1][3], fa1[cur], fb1[cur][2], fb1[cur][3]);
        }

        if (it + 1 < NIT) stsB(sbase + (uint32_t)((it + 1) % NS) * STG + 16384u, rB, t);
        if (it + 2 < NIT) ldgB<LAYER>(rB, W, c, bn, (it + 2) * 32, t);
    }

    // store coef-scaled partials
#pragma unroll
    for (int mt = 0; mt < 2; mt++) {
        int m0 = bm + wm + mt * 16 + (lane >> 2);
        int m1 = m0 + 8;
        float cs0 = g_coef[m0 * 4 + c];
        float cs1 = g_coef[m1 * 4 + c];
#pragma unroll
        for (int nt = 0; nt < 4; nt++) {
            int n = bn + wn + nt * 8 + (lane & 3) * 2;
            *(float2*)&dst[(size_t)m0 * NP + n] =
                make_float2(acc[mt][nt][0] * cs0, acc[mt][nt][1] * cs0);
            *(float2*)&dst[(size_t)m1 * NP + n] =
                make_float2(acc[mt][nt][2] * cs1, acc[mt][nt][3] * cs1);
        }
    }
}

// ---- epilogue: 2 rows per 256-thread block ----
template <int LAYER>
__global__ void __launch_bounds__(256) k_ep(const float* __restrict__ bias,
                                            float* __restrict__ out_final) {
    int tx = threadIdx.x;
    int b = blockIdx.x * 2 + (tx >> 7);
    int tr = tx & 127;
    float4 cf = *(const float4*)&g_coef[b * 4];
    float cc[4] = {cf.x, cf.y, cf.z, cf.w};
    if (LAYER < 2) {
        int n = tr * 4;
        float4 v0 = *(const float4*)&g_p[0][(size_t)b * H_ + n];
        float4 v1 = *(const float4*)&g_p[1][(size_t)b * H_ + n];
        float4 v2 = *(const float4*)&g_p[2][(size_t)b * H_ + n];
        float4 v3 = *(const float4*)&g_p[3][(size_t)b * H_ + n];
        float s0 = v0.x + v1.x + v2.x + v3.x;
        float s1 = v0.y + v1.y + v2.y + v3.y;
        float s2 = v0.z + v1.z + v2.z + v3.z;
        float s3 = v0.w + v1.w + v2.w + v3.w;
#pragma unroll
        for (int ct = 0; ct < 4; ct++) {
            float4 bb = *(const float4*)&bias[ct * H_ + n];
            s0 += cc[ct] * bb.x; s1 += cc[ct] * bb.y;
            s2 += cc[ct] * bb.z; s3 += cc[ct] * bb.w;
        }
        float* zn = ((LAYER == 0) ? g_h1 : g_h2) + (size_t)b * K1_;
        float4 w = make_float4(to_tf32(elu1(s0)), to_tf32(elu1(s1)),
                               to_tf32(elu1(s2)), to_tf32(elu1(s3)));
        *(float4*)(zn + n) = w;
    } else {
        float* o = out_final + (size_t)b * DOUT_;
        for (int n = tr; n < DOUT_; n += 128) {
            float s = g_p[0][(size_t)b * NP2_ + n] + g_p[1][(size_t)b * NP2_ + n]
                    + g_p[2][(size_t)b * NP2_ + n] + g_p[3][(size_t)b * NP2_ + n];
#pragma unroll
            for (int ct = 0; ct < 4; ct++) s += cc[ct] * bias[ct * DOUT_ + n];
            o[n] = s;
        }
    }
}

// ---------------- launch ----------------
extern "C" void kernel_launch(void* const* d_in, const int* in_sizes, int n_in,
                              void* d_out, int out_size) {
    const float* x  = (const float*)d_in[0];
    const float* W0 = (const float*)d_in[1];
    const float* W1 = (const float*)d_in[2];
    const float* W2 = (const float*)d_in[3];
    const float* b0 = (const float*)d_in[4];
    const float* b1 = (const float*)d_in[5];
    const float* b2 = (const float*)d_in[6];
    float* out = (float*)d_out;

    static int smem_set = 0;
    if (!smem_set) {
        cudaFuncSetAttribute(k_gemm<0>, cudaFuncAttributeMaxDynamicSharedMemorySize, NS * STG);
        cudaFuncSetAttribute(k_gemm<1>, cudaFuncAttributeMaxDynamicSharedMemorySize, NS * STG);
        cudaFuncSetAttribute(k_gemm<2>, cudaFuncAttributeMaxDynamicSharedMemorySize, NS * STG);
        smem_set = 1;
    }

    k_z0<<<B_, 128>>>(x);

    k_gemm<0><<<dim3(8, 8, 4), 256, NS * STG>>>(W0);
    k_ep<0><<<B_ / 2, 256>>>(b0, nullptr);
    k_gemm<1><<<dim3(8, 8, 4), 256, NS * STG>>>(W1);
    k_ep<1><<<B_ / 2, 256>>>(b1, nullptr);
    k_gemm<2><<<dim3(5, 8, 4), 256, NS * STG>>>(W2);
    k_ep<2><<<B_ / 2, 256>>>(b2, out);
}